// round 16
// baseline (speedup 1.0000x reference)
#include <cuda_runtime.h>
#include <cuda_bf16.h>
#include <cstdint>
#include <math.h>

#define DM 1024
#define NH 16
#define HD 64
#define BB 2
#define SS 2048
#define MT (BB*SS)   // 4096 rows

// tcgen05 is arch-SPECIFIC (sm_103a). The harness also runs a compute_103
// (non-a) pass where ptxas rejects tcgen05 — guard it out there.
#if defined(__CUDA_ARCH__) && defined(__CUDA_ARCH_FEAT_SM103_ALL)
#define HAS_TC 1
#else
#define HAS_TC 0
#endif

// Scratch (device globals: allocation-free rule). Device-code refs only.
__device__ float g_Q[(size_t)BB*NH*SS*HD];
__device__ float g_K[(size_t)BB*NH*SS*HD];
__device__ float g_V[(size_t)BB*NH*SS*HD];
__device__ float g_AO[(size_t)MT*DM];

// RoPE angle tables (unique angles: [s][i], i in 0..31)
__device__ float g_rcos[(size_t)SS*32];
__device__ float g_rsin[(size_t)SS*32];

// Pre-converted split-bf16 operands (hi + lo), filled by converter kernels.
__device__ __nv_bfloat16 g_Xh[(size_t)MT*DM],  g_Xl[(size_t)MT*DM];
__device__ __nv_bfloat16 g_Wth[(size_t)4*DM*DM], g_Wtl[(size_t)4*DM*DM]; // [z][n][k]
__device__ __nv_bfloat16 g_Qsh[(size_t)BB*NH*SS*HD], g_Qsl[(size_t)BB*NH*SS*HD];
__device__ __nv_bfloat16 g_Ksh[(size_t)BB*NH*SS*HD], g_Ksl[(size_t)BB*NH*SS*HD];
__device__ __nv_bfloat16 g_VTh[(size_t)BB*NH*HD*SS], g_VTl[(size_t)BB*NH*HD*SS]; // [bh][d][s]
__device__ __nv_bfloat16 g_AOh[(size_t)MT*DM], g_AOl[(size_t)MT*DM];

// split two fp32 into packed bf16x2 hi word + lo word
__device__ __forceinline__ void split2(float a, float b, uint32_t& h2, uint32_t& l2)
{
    __nv_bfloat16 ha = __float2bfloat16(a), hb = __float2bfloat16(b);
    h2 = ((uint32_t)__bfloat16_as_ushort(hb) << 16) | (uint32_t)__bfloat16_as_ushort(ha);
    __nv_bfloat16 la = __float2bfloat16(a - __bfloat162float(ha));
    __nv_bfloat16 lb = __float2bfloat16(b - __bfloat162float(hb));
    l2 = ((uint32_t)__bfloat16_as_ushort(lb) << 16) | (uint32_t)__bfloat16_as_ushort(la);
}

// fast exp via 2^f polynomial (FMA pipe, not MUFU). Valid |x| < ~80, rel err ~2e-6.
__device__ __forceinline__ float fast_exp(float x)
{
    float y = x * 1.4426950408889634f;
    float r = rintf(y);
    float f = y - r;
    float p = 1.3333558146428443e-3f;
    p = fmaf(p, f, 9.6181291076284772e-3f);
    p = fmaf(p, f, 5.5504108664821580e-2f);
    p = fmaf(p, f, 2.4022650695910072e-1f);
    p = fmaf(p, f, 6.9314718055994531e-1f);
    p = fmaf(p, f, 1.0f);
    return __int_as_float(__float_as_int(p) + (((int)r) << 23));
}

// ============================================================================
// FFMA fallback GEMM core (proven R5) — compiles on every pass.
// ============================================================================
__device__ __forceinline__ void gemm_core(
    const float* __restrict__ A, const float* __restrict__ W,
    float (*As)[132], float (*Bs)[128],
    int bm, int bn, float acc[8][8])
{
    const int tid = threadIdx.x;
    const int tx  = tid & 15;
    const int ty  = tid >> 4;
    const int a_row = tid >> 2;
    const int a_k   = (tid & 3) << 2;
    const int b_k   = tid >> 5;
    const int b_n   = (tid & 31) << 2;

    for (int k0 = 0; k0 < DM; k0 += 16) {
#pragma unroll
        for (int i = 0; i < 2; i++) {
            int r = a_row + i * 64;
            float4 v = *(const float4*)(A + (size_t)(bm + r) * DM + k0 + a_k);
            As[a_k + 0][r] = v.x; As[a_k + 1][r] = v.y;
            As[a_k + 2][r] = v.z; As[a_k + 3][r] = v.w;
        }
#pragma unroll
        for (int i = 0; i < 2; i++) {
            int kk = b_k + i * 8;
            *(float4*)&Bs[kk][b_n] =
                *(const float4*)(W + (size_t)(k0 + kk) * DM + bn + b_n);
        }
        __syncthreads();
#pragma unroll
        for (int k = 0; k < 16; k++) {
            float a_reg[8], b_reg[8];
            *(float4*)&a_reg[0] = *(float4*)&As[k][ty * 4];
            *(float4*)&a_reg[4] = *(float4*)&As[k][ty * 4 + 64];
            *(float4*)&b_reg[0] = *(float4*)&Bs[k][tx * 4];
            *(float4*)&b_reg[4] = *(float4*)&Bs[k][tx * 4 + 64];
#pragma unroll
            for (int i = 0; i < 8; i++)
#pragma unroll
                for (int j = 0; j < 8; j++)
                    acc[i][j] = fmaf(a_reg[i], b_reg[j], acc[i][j]);
        }
        __syncthreads();
    }
}

#if HAS_TC
// ============================================================================
// PTX helpers (sm_103a pass only)
// ============================================================================
__device__ __forceinline__ uint32_t smem_to_u32(const void* p) {
    uint32_t a;
    asm("{ .reg .u64 t; cvta.to.shared.u64 t, %1; cvt.u32.u64 %0, t; }"
        : "=r"(a) : "l"(p));
    return a;
}

#define SMEM_SWIZZLE_128B(off) ((off) ^ (((off) >> 3) & 0x70))

static constexpr uint64_t SMEM_DESC_BASE_SW128 =
    (uint64_t(2)  << 61) | (uint64_t(1) << 46) | (uint64_t(64) << 32) | (uint64_t(1) << 16);
#define MAKE_SMEM_DESC(base_addr) \
    (SMEM_DESC_BASE_SW128 | ((uint64_t)((base_addr) >> 4) & 0x3FFF))

#define TCGEN05_ALLOC(smem_result_addr, nCols) \
    asm volatile("tcgen05.alloc.cta_group::1.sync.aligned.shared::cta.b32 [%0], %1;" \
        :: "r"((uint32_t)(smem_result_addr)), "r"((uint32_t)(nCols)) : "memory")
#define TCGEN05_DEALLOC(tmem_addr, nCols) \
    asm volatile("tcgen05.dealloc.cta_group::1.sync.aligned.b32 %0, %1;" \
        :: "r"(tmem_addr), "r"((uint32_t)(nCols)))
#define TCGEN05_COMMIT(mbar) \
    asm volatile("tcgen05.commit.cta_group::1.mbarrier::arrive::one.shared::cluster.b64 [%0];" \
        :: "r"((uint32_t)(mbar)) : "memory")
#define TCGEN05_WAIT_LD() asm volatile("tcgen05.wait::ld.sync.aligned;" ::: "memory")
#define TCGEN05_WAIT_ST() asm volatile("tcgen05.wait::st.sync.aligned;" ::: "memory")
#define TCGEN05_FENCE_BEFORE() asm volatile("tcgen05.fence::before_thread_sync;" ::: "memory")
#define TCGEN05_FENCE_AFTER() asm volatile("tcgen05.fence::after_thread_sync;" ::: "memory")
#define FENCE_PROXY_ASYNC_SHARED_CTA() \
    asm volatile("fence.proxy.async.shared::cta;" ::: "memory")
#define MBARRIER_INIT(mbar, count) \
    asm volatile("mbarrier.init.shared.b64 [%0], %1;" \
        :: "r"((uint32_t)(mbar)), "r"((uint32_t)(count)) : "memory")

#define MBARRIER_WAIT_PARITY(mbar, parity) do {                                   \
    uint32_t _m = (uint32_t)(mbar); uint32_t _p = (uint32_t)(parity);             \
    uint32_t _done;                                                               \
    asm volatile("{\n\t.reg .pred p;\n\t"                                         \
        "mbarrier.try_wait.parity.acquire.cta.shared::cta.b64 p, [%1], %2;\n\t"   \
        "selp.b32 %0, 1, 0, p;\n\t}"                                              \
        : "=r"(_done) : "r"(_m), "r"(_p) : "memory");                             \
    if (!_done) {                                                                 \
        asm volatile("{\n\t.reg .pred P1;\n\t"                                    \
            "WAIT_LOOP_%=:\n\t"                                                   \
            "mbarrier.try_wait.parity.acquire.cta.shared::cta.b64 P1, [%0], %1, 0x989680;\n\t" \
            "@P1 bra.uni WAIT_DONE_%=;\n\t"                                       \
            "bra.uni WAIT_LOOP_%=;\n\t"                                           \
            "WAIT_DONE_%=:\n\t}"                                                  \
            :: "r"(_m), "r"(_p) : "memory");                                      \
    }                                                                             \
} while (0)

#define TCGEN05_LD_32X32B_X32(r, tmem_addr) \
    asm volatile( \
        "tcgen05.ld.sync.aligned.32x32b.x32.b32 " \
        "{%0, %1, %2, %3, %4, %5, %6, %7, " \
        " %8, %9, %10, %11, %12, %13, %14, %15, " \
        " %16, %17, %18, %19, %20, %21, %22, %23, " \
        " %24, %25, %26, %27, %28, %29, %30, %31}, [%32];" \
        : "=r"((r)[0]),  "=r"((r)[1]),  "=r"((r)[2]),  "=r"((r)[3]), \
          "=r"((r)[4]),  "=r"((r)[5]),  "=r"((r)[6]),  "=r"((r)[7]), \
          "=r"((r)[8]),  "=r"((r)[9]),  "=r"((r)[10]), "=r"((r)[11]), \
          "=r"((r)[12]), "=r"((r)[13]), "=r"((r)[14]), "=r"((r)[15]), \
          "=r"((r)[16]), "=r"((r)[17]), "=r"((r)[18]), "=r"((r)[19]), \
          "=r"((r)[20]), "=r"((r)[21]), "=r"((r)[22]), "=r"((r)[23]), \
          "=r"((r)[24]), "=r"((r)[25]), "=r"((r)[26]), "=r"((r)[27]), \
          "=r"((r)[28]), "=r"((r)[29]), "=r"((r)[30]), "=r"((r)[31]) \
        : "r"(tmem_addr))

#define TCGEN05_ST_32X32B_X32(tmem_addr, r) \
    asm volatile( \
        "tcgen05.st.sync.aligned.32x32b.x32.b32 [%0], " \
        "{%1, %2, %3, %4, %5, %6, %7, %8, " \
        " %9, %10, %11, %12, %13, %14, %15, %16, " \
        " %17, %18, %19, %20, %21, %22, %23, %24, " \
        " %25, %26, %27, %28, %29, %30, %31, %32};" \
        :: "r"(tmem_addr), \
           "r"((r)[0]),  "r"((r)[1]),  "r"((r)[2]),  "r"((r)[3]), \
           "r"((r)[4]),  "r"((r)[5]),  "r"((r)[6]),  "r"((r)[7]), \
           "r"((r)[8]),  "r"((r)[9]),  "r"((r)[10]), "r"((r)[11]), \
           "r"((r)[12]), "r"((r)[13]), "r"((r)[14]), "r"((r)[15]), \
           "r"((r)[16]), "r"((r)[17]), "r"((r)[18]), "r"((r)[19]), \
           "r"((r)[20]), "r"((r)[21]), "r"((r)[22]), "r"((r)[23]), \
           "r"((r)[24]), "r"((r)[25]), "r"((r)[26]), "r"((r)[27]), \
           "r"((r)[28]), "r"((r)[29]), "r"((r)[30]), "r"((r)[31]) \
        : "memory")

__device__ __forceinline__ void mma_bf16_ss(
    uint32_t d_tmem, uint64_t a_desc, uint64_t b_desc, uint32_t idesc, uint32_t enable)
{
    asm volatile(
        "{\n\t.reg .pred p;\n\t"
        "setp.ne.u32 p, %5, 0;\n\t"
        "tcgen05.mma.cta_group::1.kind::f16 [%0], %1, %2, %3, {%4, %4, %4, %4}, p;\n\t"
        "}"
        :: "r"(d_tmem), "l"(a_desc), "l"(b_desc), "r"(idesc), "r"(0u), "r"(enable)
        : "memory");
}

__device__ __forceinline__ void mma_bf16_ts(
    uint32_t d_tmem, uint32_t a_tmem, uint64_t b_desc, uint32_t idesc, uint32_t enable)
{
    asm volatile(
        "{\n\t.reg .pred p;\n\t"
        "setp.ne.u32 p, %5, 0;\n\t"
        "tcgen05.mma.cta_group::1.kind::f16 [%0], [%1], %2, %3, {%4, %4, %4, %4}, p;\n\t"
        "}"
        :: "r"(d_tmem), "r"(a_tmem), "l"(b_desc), "r"(idesc), "r"(0u), "r"(enable)
        : "memory");
}

static constexpr uint32_t MMA_IDESC =           // N=128, M=128
    (1u << 4) | (1u << 7) | (1u << 10) | ((128u / 8) << 17) | ((128u / 16) << 24);
static constexpr uint32_t IDESC_PV =            // N=64, M=128
    (1u << 4) | (1u << 7) | (1u << 10) | ((64u / 8) << 17) | ((128u / 16) << 24);
#endif  // HAS_TC

// GEMM stage (M=256 tiles): Ah 32K | Al 32K | Bh 16K | Bl 16K = 96K
#define STAGE_SZ 98304
#define DYN_SMEM (1024 + 2*STAGE_SZ)     // 197632

#if HAS_TC
// ============================================================================
// Tensor-core GEMM tile, M=256 x N=128 (unchanged from passing R15)
// ============================================================================
__device__ void tc_gemm_tile(
    const __nv_bfloat16* __restrict__ Ah, const __nv_bfloat16* __restrict__ Al,
    const __nv_bfloat16* __restrict__ Bh, const __nv_bfloat16* __restrict__ Bl,
    char* sm, uint32_t smb, int bm, int bn, uint32_t tmem)
{
    const int tid = threadIdx.x;
    int phase0 = 0, phase1 = 0;

    for (int c = 0; c < 16; c++) {
        const int stg = c & 1;
        if (c >= 2) {
            if (stg == 0) { MBARRIER_WAIT_PARITY(smb + 16, phase0); phase0 ^= 1; }
            else          { MBARRIER_WAIT_PARITY(smb + 24, phase1); phase1 ^= 1; }
        }
        char* As_h = sm + 1024 + stg * STAGE_SZ;   // 256 rows x 128B
        char* As_l = As_h + 32768;
        char* Bs_h = As_h + 65536;                 // 128 rows x 128B
        char* Bs_l = As_h + 81920;

#pragma unroll
        for (int i = 0; i < 8; i++) {
            int lin = tid + 256 * i;
            int row = lin >> 3, kf = lin & 7;
            uint32_t sw = SMEM_SWIZZLE_128B((uint32_t)(row * 128 + kf * 16));
            size_t ga = (size_t)(bm + row) * DM + c * 64 + kf * 8;
            *(uint4*)(As_h + sw) = *(const uint4*)(Ah + ga);
            *(uint4*)(As_l + sw) = *(const uint4*)(Al + ga);
        }
#pragma unroll
        for (int i = 0; i < 4; i++) {
            int lin = tid + 256 * i;
            int row = lin >> 3, kf = lin & 7;
            uint32_t sw = SMEM_SWIZZLE_128B((uint32_t)(row * 128 + kf * 16));
            size_t gb = (size_t)(bn + row) * DM + c * 64 + kf * 8;
            *(uint4*)(Bs_h + sw) = *(const uint4*)(Bh + gb);
            *(uint4*)(Bs_l + sw) = *(const uint4*)(Bl + gb);
        }
        __syncthreads();

        if (tid == 0) {
            FENCE_PROXY_ASYNC_SHARED_CTA();
            uint64_t dah  = MAKE_SMEM_DESC(smb + 1024 + stg * STAGE_SZ);
            uint64_t dah2 = dah + (16384 >> 4);   // A rows 128-255
            uint64_t dal  = dah + (32768 >> 4);
            uint64_t dal2 = dal + (16384 >> 4);
            uint64_t dbh  = dah + (65536 >> 4);
            uint64_t dbl  = dah + (81920 >> 4);
            uint32_t en = (c != 0);
#pragma unroll
            for (int ks = 0; ks < 4; ks++) {
                uint64_t off = ks * 2;
                uint32_t e = (ks == 0) ? en : 1;
                mma_bf16_ss(tmem,       dah  + off, dbh + off, MMA_IDESC, e);
                mma_bf16_ss(tmem,       dah  + off, dbl + off, MMA_IDESC, 1);
                mma_bf16_ss(tmem,       dal  + off, dbh + off, MMA_IDESC, 1);
                mma_bf16_ss(tmem + 128, dah2 + off, dbh + off, MMA_IDESC, e);
                mma_bf16_ss(tmem + 128, dah2 + off, dbl + off, MMA_IDESC, 1);
                mma_bf16_ss(tmem + 128, dal2 + off, dbh + off, MMA_IDESC, 1);
            }
            TCGEN05_COMMIT(smb + 16 + stg * 8);
        }
    }
    MBARRIER_WAIT_PARITY(smb + 16, phase0);
    MBARRIER_WAIT_PARITY(smb + 24, phase1);
    TCGEN05_FENCE_AFTER();
}
#endif  // HAS_TC

// ============================================================================
// Converter kernels (unchanged)
// ============================================================================

__global__ __launch_bounds__(256) void convert_w_kernel(
    const float* __restrict__ Wq, const float* __restrict__ Wk,
    const float* __restrict__ Wv, const float* __restrict__ Wo)
{
    __shared__ float tile[64 * 65];
    const int z = blockIdx.z;
    const float* W = (z == 0) ? Wq : (z == 1) ? Wk : (z == 2) ? Wv : Wo;
    const int kt = blockIdx.x, nt = blockIdx.y;

#pragma unroll
    for (int i = 0; i < 16; i++) {
        int lin = threadIdx.x + 256 * i;
        int r = lin >> 6, cc = lin & 63;
        tile[r * 65 + cc] = W[(size_t)(kt * 64 + r) * DM + nt * 64 + cc];
    }
    __syncthreads();
#pragma unroll
    for (int i = 0; i < 2; i++) {
        int lin = threadIdx.x + 256 * i;
        int n = lin >> 3, kg = lin & 7;
        float v[8];
#pragma unroll
        for (int j = 0; j < 8; j++) v[j] = tile[(kg * 8 + j) * 65 + n];
        uint4 H, L;
        split2(v[0], v[1], H.x, L.x); split2(v[2], v[3], H.y, L.y);
        split2(v[4], v[5], H.z, L.z); split2(v[6], v[7], H.w, L.w);
        size_t o = ((size_t)z * DM + nt * 64 + n) * DM + kt * 64 + kg * 8;
        *(uint4*)(g_Wth + o) = H;
        *(uint4*)(g_Wtl + o) = L;
    }
}

__global__ __launch_bounds__(256) void convert_x_kernel(const float* __restrict__ x)
{
    size_t g = ((size_t)blockIdx.x * 256 + threadIdx.x) * 8;
    float4 v0 = *(const float4*)(x + g);
    float4 v1 = *(const float4*)(x + g + 4);
    uint4 H, L;
    split2(v0.x, v0.y, H.x, L.x); split2(v0.z, v0.w, H.y, L.y);
    split2(v1.x, v1.y, H.z, L.z); split2(v1.z, v1.w, H.w, L.w);
    *(uint4*)(g_Xh + g) = H;
    *(uint4*)(g_Xl + g) = L;
}

__global__ __launch_bounds__(256) void convert_v_kernel()
{
    __shared__ float tile[64 * 65];
    const int bh = blockIdx.y;
    const int s0 = blockIdx.x * 64;
    const float* V = g_V + (size_t)bh * SS * HD;

#pragma unroll
    for (int i = 0; i < 16; i++) {
        int lin = threadIdx.x + 256 * i;
        int r = lin >> 6, d = lin & 63;
        tile[r * 65 + d] = V[(size_t)(s0 + r) * HD + d];
    }
    __syncthreads();
#pragma unroll
    for (int i = 0; i < 2; i++) {
        int lin = threadIdx.x + 256 * i;
        int d = lin >> 3, sg = lin & 7;
        float v[8];
#pragma unroll
        for (int j = 0; j < 8; j++) v[j] = tile[(sg * 8 + j) * 65 + d];
        uint4 H, L;
        split2(v[0], v[1], H.x, L.x); split2(v[2], v[3], H.y, L.y);
        split2(v[4], v[5], H.z, L.z); split2(v[6], v[7], H.w, L.w);
        size_t o = ((size_t)bh * HD + d) * SS + s0 + sg * 8;
        *(uint4*)(g_VTh + o) = H;
        *(uint4*)(g_VTl + o) = L;
    }
}

// ---------------------------------------------------------------------------
// QKV projection (M=256 tiles, unchanged from passing R15)
// ---------------------------------------------------------------------------
__global__ __launch_bounds__(256, 1) void qkv_tc_kernel(
    const float* __restrict__ X,
    const float* __restrict__ Wq, const float* __restrict__ Wk, const float* __restrict__ Wv,
    const float* __restrict__ bq, const float* __restrict__ bk, const float* __restrict__ bv)
{
    extern __shared__ char sm[];
    const float* Wf; const float* bias; float* outp;
    if (blockIdx.z == 0)      { Wf = Wq; bias = bq; outp = g_Q; }
    else if (blockIdx.z == 1) { Wf = Wk; bias = bk; outp = g_K; }
    else                      { Wf = Wv; bias = bv; outp = g_V; }

    const int bm = blockIdx.y * 256, bn = blockIdx.x * 128;

#if HAS_TC
    (void)X; (void)Wf;
    const uint32_t smb = smem_to_u32(sm);
    const int tid = threadIdx.x, wid = tid >> 5, lane = tid & 31;

    if (wid == 0) TCGEN05_ALLOC(smb + 0, 512);
    if (tid == 0) { MBARRIER_INIT(smb + 16, 1); MBARRIER_INIT(smb + 24, 1); }
    __syncthreads();
    uint32_t tmem;
    asm volatile("ld.shared.b32 %0, [%1];" : "=r"(tmem) : "r"(smb + 0));

    const __nv_bfloat16* Bh = g_Wth + (size_t)blockIdx.z * DM * DM;
    const __nv_bfloat16* Bl = g_Wtl + (size_t)blockIdx.z * DM * DM;
    tc_gemm_tile(g_Xh, g_Xl, Bh, Bl, sm, smb, bm, bn, tmem);

    {
        const int mh = wid >> 2, sp = wid & 3;
        float* ep = (float*)(sm + 1024 + wid * 4352);
#pragma unroll
        for (int nc = 0; nc < 4; nc++) {
            uint32_t r[32];
            TCGEN05_LD_32X32B_X32(r, tmem + mh * 128 + nc * 32);
            TCGEN05_WAIT_LD();
#pragma unroll
            for (int cc = 0; cc < 32; cc++) ep[lane * 33 + cc] = __uint_as_float(r[cc]);
            __syncwarp();
            int n = bn + nc * 32 + lane;
            float bval = bias[n];
            int h = n >> 6, dh = n & 63;
#pragma unroll
            for (int rr = 0; rr < 32; rr++) {
                int m = bm + mh * 128 + sp * 32 + rr;
                int b = m >> 11, s = m & (SS - 1);
                outp[(((size_t)(b * NH + h)) * SS + s) * HD + dh] = ep[rr * 33 + lane] + bval;
            }
            __syncwarp();
        }
    }
    __syncthreads();
    if (wid == 0) TCGEN05_DEALLOC(tmem, 512);
#else
    float (*As)[132] = (float(*)[132])sm;
    float (*Bs)[128] = (float(*)[128])(sm + 16 * 132 * 4);
    const int tx = threadIdx.x & 15, ty = threadIdx.x >> 4;
    for (int h2 = 0; h2 < 2; h2++) {
        float acc[8][8] = {};
        gemm_core(X, Wf, As, Bs, bm + h2 * 128, bn, acc);
#pragma unroll
        for (int i = 0; i < 8; i++) {
            int m = bm + h2 * 128 + ty * 4 + (i & 3) + (i >> 2) * 64;
            int b = m >> 11, s = m & (SS - 1);
#pragma unroll
            for (int j = 0; j < 8; j++) {
                int n  = bn + tx * 4 + (j & 3) + (j >> 2) * 64;
                int h  = n >> 6, dh = n & 63;
                outp[(((size_t)(b * NH + h)) * SS + s) * HD + dh] = acc[i][j] + bias[n];
            }
        }
        __syncthreads();
    }
#endif
}

// ---------------------------------------------------------------------------
// Output projection (M=256 tiles, unchanged from passing R15)
// ---------------------------------------------------------------------------
__global__ __launch_bounds__(256, 1) void out_tc_kernel(
    const float* __restrict__ W, const float* __restrict__ bias, float* __restrict__ outp)
{
    extern __shared__ char sm[];
    const int bm = blockIdx.y * 256, bn = blockIdx.x * 128;

#if HAS_TC
    (void)W;
    const uint32_t smb = smem_to_u32(sm);
    const int tid = threadIdx.x, wid = tid >> 5, lane = tid & 31;

    if (wid == 0) TCGEN05_ALLOC(smb + 0, 512);
    if (tid == 0) { MBARRIER_INIT(smb + 16, 1); MBARRIER_INIT(smb + 24, 1); }
    __syncthreads();
    uint32_t tmem;
    asm volatile("ld.shared.b32 %0, [%1];" : "=r"(tmem) : "r"(smb + 0));

    tc_gemm_tile(g_AOh, g_AOl, g_Wth + (size_t)3 * DM * DM, g_Wtl + (size_t)3 * DM * DM,
                 sm, smb, bm, bn, tmem);

    {
        const int mh = wid >> 2, sp = wid & 3;
        float* ep = (float*)(sm + 1024 + wid * 4352);
#pragma unroll
        for (int nc = 0; nc < 4; nc++) {
            uint32_t r[32];
            TCGEN05_LD_32X32B_X32(r, tmem + mh * 128 + nc * 32);
            TCGEN05_WAIT_LD();
#pragma unroll
            for (int cc = 0; cc < 32; cc++) ep[lane * 33 + cc] = __uint_as_float(r[cc]);
            __syncwarp();
            int n = bn + nc * 32 + lane;
            float bval = bias[n];
#pragma unroll
            for (int rr = 0; rr < 32; rr++) {
                int m = bm + mh * 128 + sp * 32 + rr;
                outp[(size_t)m * DM + n] = ep[rr * 33 + lane] + bval;
            }
            __syncwarp();
        }
    }
    __syncthreads();
    if (wid == 0) TCGEN05_DEALLOC(tmem, 512);
#else
    float (*As)[132] = (float(*)[132])sm;
    float (*Bs)[128] = (float(*)[128])(sm + 16 * 132 * 4);
    const int tx = threadIdx.x & 15, ty = threadIdx.x >> 4;
    for (int h2 = 0; h2 < 2; h2++) {
        float acc[8][8] = {};
        gemm_core(g_AO, W, As, Bs, bm + h2 * 128, bn, acc);
#pragma unroll
        for (int i = 0; i < 8; i++) {
            int m = bm + h2 * 128 + ty * 4 + (i & 3) + (i >> 2) * 64;
#pragma unroll
            for (int j = 0; j < 8; j++) {
                int n = bn + tx * 4 + (j & 3) + (j >> 2) * 64;
                outp[(size_t)m * DM + n] = acc[i][j] + bias[n];
            }
        }
        __syncthreads();
    }
#endif
}

// ---------------------------------------------------------------------------
// RoPE: angle table + memory-bound apply (unchanged)
// ---------------------------------------------------------------------------
__global__ __launch_bounds__(256) void rope_table_kernel()
{
    int idx = blockIdx.x * blockDim.x + threadIdx.x;
    int i = idx & 31;
    int s = idx >> 5;
    float invf = powf(10000.0f, -((float)(2 * i)) / (float)HD);
    float th   = (float)s * invf;
    g_rcos[idx] = (float)cos((double)th);
    g_rsin[idx] = (float)sin((double)th);
}

__global__ __launch_bounds__(256) void rope_kernel()
{
    int idx = blockIdx.x * blockDim.x + threadIdx.x;
    const int total = BB * NH * SS * 32;
    if (idx >= total) return;
    int i   = idx & 31;
    int bhs = idx >> 5;
    int s   = bhs & (SS - 1);

    float c  = g_rcos[s * 32 + i];
    float sn = g_rsin[s * 32 + i];

    size_t base = (size_t)bhs * HD;
    float q0 = g_Q[base + i], q1 = g_Q[base + i + 32];
    float k0 = g_K[base + i], k1 = g_K[base + i + 32];
    float qa = q0 * c - q1 * sn, qb = q1 * c + q0 * sn;
    float ka = k0 * c - k1 * sn, kb = k1 * c + k0 * sn;
#if HAS_TC
    qa *= 0.125f; qb *= 0.125f;
    __nv_bfloat16 h;
    h = __float2bfloat16(qa); g_Qsh[base + i]      = h; g_Qsl[base + i]      = __float2bfloat16(qa - __bfloat162float(h));
    h = __float2bfloat16(qb); g_Qsh[base + i + 32] = h; g_Qsl[base + i + 32] = __float2bfloat16(qb - __bfloat162float(h));
    h = __float2bfloat16(ka); g_Ksh[base + i]      = h; g_Ksl[base + i]      = __float2bfloat16(ka - __bfloat162float(h));
    h = __float2bfloat16(kb); g_Ksh[base + i + 32] = h; g_Ksl[base + i + 32] = __float2bfloat16(kb - __bfloat162float(h));
#else
    g_Q[base + i] = qa; g_Q[base + i + 32] = qb;
    g_K[base + i] = ka; g_K[base + i + 32] = kb;
#endif
}

// ---------------------------------------------------------------------------
// Flash attention. TC path: double-buffered K/V stages AND double-buffered S
// in TMEM. Per iter: wait PV(kt-1) -> load stage(kt+1) -> issue S(kt+1) into
// alternate S buffer -> wait S(kt) -> softmax(S(kt)) [overlapped by S(kt+1)
// on the tensor pipe] -> STTM P -> PV(kt).
// TMEM: S0@0(128) O@128(64) Ph@192(64) Pl@256(64) S1@320(128); alloc 512.
// ---------------------------------------------------------------------------
#define OFF_QH 1024
#define OFF_QL (OFF_QH + 16384)
#define OFF_S0 (OFF_QL + 16384)          // stage base: 33792
#define FSTG 65536
#define FLASH_SMEM (OFF_S0 + 2*FSTG)     // 164864
#define TM_S0 0
#define TM_O 128
#define TM_PH 192
#define TM_PL 256
#define TM_S1 320

__global__ __launch_bounds__(256, 1) void flash_kernel()
{
#if HAS_TC
    extern __shared__ char sm[];
    const uint32_t smb = smem_to_u32(sm);
    const int tid = threadIdx.x, wid = tid >> 5, lane = tid & 31;
    const int bh = blockIdx.y;
    const int q0 = blockIdx.x * 128;

    if (wid == 0) TCGEN05_ALLOC(smb + 0, 512);
    if (tid == 0) { MBARRIER_INIT(smb + 8, 1); MBARRIER_INIT(smb + 16, 1); }
    __syncthreads();
    uint32_t tmem;
    asm volatile("ld.shared.b32 %0, [%1];" : "=r"(tmem) : "r"(smb + 0));

    // Q tile copy (pre-scaled, pre-split)
#pragma unroll
    for (int i = 0; i < 4; i++) {
        int lin = tid + 256 * i;
        int row = lin >> 3, kf = lin & 7;
        uint32_t sw = SMEM_SWIZZLE_128B((uint32_t)(row * 128 + kf * 16));
        size_t ga = ((size_t)bh * SS + q0 + row) * HD + kf * 8;
        *(uint4*)(sm + OFF_QH + sw) = *(const uint4*)(g_Qsh + ga);
        *(uint4*)(sm + OFF_QL + sw) = *(const uint4*)(g_Qsl + ga);
    }

    // stage loader: K split + V (pre-transposed [d][s]) split into stage st
    auto load_stage = [&](int kt, int st) {
        char* base = sm + OFF_S0 + st * FSTG;
#pragma unroll
        for (int i = 0; i < 4; i++) {
            int lin = tid + 256 * i;
            int row = lin >> 3, kf = lin & 7;
            uint32_t sw = SMEM_SWIZZLE_128B((uint32_t)(row * 128 + kf * 16));
            size_t ga = ((size_t)bh * SS + kt * 128 + row) * HD + kf * 8;
            *(uint4*)(base + sw)         = *(const uint4*)(g_Ksh + ga);
            *(uint4*)(base + 16384 + sw) = *(const uint4*)(g_Ksl + ga);
        }
#pragma unroll
        for (int i = 0; i < 4; i++) {
            int lin = tid + 256 * i;
            int d = lin >> 4, kg = lin & 15;
            int sub = kg >> 3;
            uint32_t sw = SMEM_SWIZZLE_128B((uint32_t)(d * 128 + (kg & 7) * 16));
            size_t ga = ((size_t)bh * HD + d) * SS + kt * 128 + kg * 8;
            *(uint4*)(base + 32768 + sub * 8192 + sw) = *(const uint4*)(g_VTh + ga);
            *(uint4*)(base + 49152 + sub * 8192 + sw) = *(const uint4*)(g_VTl + ga);
        }
    };

    const uint64_t qh_d = MAKE_SMEM_DESC(smb + OFF_QH);
    const uint64_t ql_d = MAKE_SMEM_DESC(smb + OFF_QL);

    // S-issue helper: S tile for K in stage st into S buffer sb
    auto issue_S = [&](int st, int sb) {
        const uint32_t stb2 = smb + OFF_S0 + st * FSTG;
        FENCE_PROXY_ASYNC_SHARED_CTA();
        uint64_t kh_d = MAKE_SMEM_DESC(stb2);
        uint64_t kl_d = MAKE_SMEM_DESC(stb2 + 16384);
        uint32_t sbase = tmem + (sb ? TM_S1 : TM_S0);
        uint32_t en = 0;
#pragma unroll
        for (int ks = 0; ks < 4; ks++) {
            uint64_t off = ks * 2;
            mma_bf16_ss(sbase, qh_d + off, kh_d + off, MMA_IDESC, en); en = 1;
            mma_bf16_ss(sbase, qh_d + off, kl_d + off, MMA_IDESC, 1);
            mma_bf16_ss(sbase, ql_d + off, kh_d + off, MMA_IDESC, 1);
        }
        TCGEN05_COMMIT(smb + 8);
    };

    // prologue: stage 0 holds kt=0; issue S(0) into buffer 0
    load_stage(0, 0);
    __syncthreads();
    if (tid == 0) issue_S(0, 0);

    float lrow = 0.0f;
    int ph_s = 0, ph_o = 0;

    for (int kt = 0; kt < SS / 128; kt++) {
        const int st = kt & 1;
        const uint32_t stb = smb + OFF_S0 + st * FSTG;

        // wait PV(kt-1): frees stage 1-st (K fully read by S(kt), which
        // precedes PV(kt-1) in the in-order tensor queue; V read by PV(kt-1))
        if (kt > 0) { MBARRIER_WAIT_PARITY(smb + 16, ph_o); ph_o ^= 1; }

        // prefetch next tile and immediately queue its S-MMA (runs on the
        // tensor pipe while we do softmax below)
        if (kt + 1 < SS / 128) {
            load_stage(kt + 1, 1 - st);
            __syncthreads();
            if (tid == 0) issue_S(1 - st, (kt + 1) & 1);
        }

        // wait S(kt)
        MBARRIER_WAIT_PARITY(smb + 8, ph_s); ph_s ^= 1;
        TCGEN05_FENCE_AFTER();

        // softmax: all 8 warps; warp w handles column-half (w>>2) for its lanes
        {
            const uint32_t sbase = tmem + ((kt & 1) ? TM_S1 : TM_S0);
            const uint32_t woff = (uint32_t)(wid & 3) << 21;
            const int hw = wid >> 2;
            uint32_t s0[32], s1[32];
            TCGEN05_LD_32X32B_X32(s0, sbase + hw * 64);
            TCGEN05_LD_32X32B_X32(s1, sbase + hw * 64 + 32);
            TCGEN05_WAIT_LD();
            uint32_t phw[32], plw[32];
#pragma unroll
            for (int w = 0; w < 32; w++) {
                float pe, pd;
                if (w < 16) {
                    pe = fast_exp(__uint_as_float(s0[2 * w]));
                    pd = fast_exp(__uint_as_float(s0[2 * w + 1]));
                } else {
                    pe = fast_exp(__uint_as_float(s1[2 * w - 32]));
                    pd = fast_exp(__uint_as_float(s1[2 * w - 31]));
                }
                lrow += pe + pd;
                split2(pe, pd, phw[w], plw[w]);
            }
            TCGEN05_ST_32X32B_X32(tmem + TM_PH + hw * 32 + woff, phw);
            TCGEN05_ST_32X32B_X32(tmem + TM_PL + hw * 32 + woff, plw);
            TCGEN05_WAIT_ST();
            TCGEN05_FENCE_BEFORE();
        }
        __syncthreads();   // all STTM done

        // issue PV(kt) from stage st's V
        if (tid == 0) {
            TCGEN05_FENCE_AFTER();
            uint64_t vth_d0 = MAKE_SMEM_DESC(stb + 32768);
            uint64_t vth_d1 = MAKE_SMEM_DESC(stb + 32768 + 8192);
            uint64_t vtl_d0 = MAKE_SMEM_DESC(stb + 49152);
            uint64_t vtl_d1 = MAKE_SMEM_DESC(stb + 49152 + 8192);
            uint32_t en = (kt != 0);
#pragma unroll
            for (int ks = 0; ks < 8; ks++) {
                uint32_t a_off = ks * 8;
                uint64_t b_off = (uint64_t)(ks & 3) * 2;
                uint64_t bh_dsc = (ks < 4 ? vth_d0 : vth_d1) + b_off;
                uint64_t bl_dsc = (ks < 4 ? vtl_d0 : vtl_d1) + b_off;
                mma_bf16_ts(tmem + TM_O, tmem + TM_PH + a_off, bh_dsc, IDESC_PV, en); en = 1;
                mma_bf16_ts(tmem + TM_O, tmem + TM_PH + a_off, bl_dsc, IDESC_PV, 1);
                mma_bf16_ts(tmem + TM_O, tmem + TM_PL + a_off, bh_dsc, IDESC_PV, 1);
            }
            TCGEN05_COMMIT(smb + 16);
        }
    }

    MBARRIER_WAIT_PARITY(smb + 16, ph_o);
    TCGEN05_FENCE_AFTER();

    // combine half-sums, normalize, write split-bf16 AO
    __syncthreads();
    float* slr = (float*)(sm + OFF_QH);
    slr[tid] = lrow;
    __syncthreads();
    if (wid < 4) {
        float ltot = slr[tid] + slr[tid + 128];
        uint32_t o0[32], o1[32];
        TCGEN05_LD_32X32B_X32(o0, tmem + TM_O);
        TCGEN05_LD_32X32B_X32(o1, tmem + TM_O + 32);
        TCGEN05_WAIT_LD();
        float inv = 1.0f / ltot;
        int b = bh >> 4, h = bh & 15;
        int s = q0 + wid * 32 + lane;
        size_t off = ((size_t)(b * SS + s)) * DM + h * HD;
#pragma unroll
        for (int g = 0; g < 8; g++) {
            float v[8];
#pragma unroll
            for (int j = 0; j < 8; j++) {
                int c = g * 8 + j;
                v[j] = (c < 32 ? __uint_as_float(o0[c]) : __uint_as_float(o1[c - 32])) * inv;
            }
            uint4 H, L;
            split2(v[0], v[1], H.x, L.x); split2(v[2], v[3], H.y, L.y);
            split2(v[4], v[5], H.z, L.z); split2(v[6], v[7], H.w, L.w);
            *(uint4*)(g_AOh + off + g * 8) = H;
            *(uint4*)(g_AOl + off + g * 8) = L;
        }
    }
    __syncthreads();
    if (wid == 0) TCGEN05_DEALLOC(tmem, 512);

#else  // ------- FFMA fallback: R5 flash over two 64-row halves -------
    __shared__ float Qt[64][64];
    __shared__ float KtPs[64][64];
    __shared__ float Vs[64][64];

    const int bh = blockIdx.y;
    const float* Qg = g_Q + (size_t)bh * SS * HD;
    const float* Kg = g_K + (size_t)bh * SS * HD;
    const float* Vg = g_V + (size_t)bh * SS * HD;

    const int tid = threadIdx.x;
    const int tx = tid & 15, ty = tid >> 4;
    const int lr = tid >> 2;
    const int lk = (tid & 3) << 2;

    for (int half = 0; half < 2; half++) {
        const int q0 = blockIdx.x * 128 + half * 64;
        __syncthreads();
#pragma unroll
        for (int u = 0; u < 4; u++) {
            int kk = lk + u * 16;
            float4 v = *(const float4*)(Qg + (size_t)(q0 + lr) * HD + kk);
            Qt[kk + 0][lr] = v.x; Qt[kk + 1][lr] = v.y;
            Qt[kk + 2][lr] = v.z; Qt[kk + 3][lr] = v.w;
        }

        float o[4][4] = {};
        float m_run[4], l_run[4];
#pragma unroll
        for (int i = 0; i < 4; i++) { m_run[i] = -1e30f; l_run[i] = 0.0f; }

        for (int kt = 0; kt < SS / 64; kt++) {
            const int kv0 = kt * 64;
            __syncthreads();
#pragma unroll
            for (int u = 0; u < 4; u++) {
                int kk = lk + u * 16;
                float4 v = *(const float4*)(Kg + (size_t)(kv0 + lr) * HD + kk);
                KtPs[kk + 0][lr] = v.x;
                KtPs[kk + 1][lr] = v.y;
                KtPs[kk + 2][lr] = v.z;
                KtPs[kk + 3][lr] = v.w;
                float4 w = *(const float4*)(Vg + (size_t)(kv0 + lr) * HD + kk);
                *(float4*)&Vs[lr][kk] = w;
            }
            __syncthreads();

            float sf[4][4] = {};
#pragma unroll 8
            for (int k = 0; k < 64; k++) {
                float4 a = *(const float4*)&Qt[k][ty * 4];
                float4 b = *(const float4*)&KtPs[k][tx * 4];
                float ar[4] = {a.x, a.y, a.z, a.w};
                float br[4] = {b.x, b.y, b.z, b.w};
#pragma unroll
                for (int i = 0; i < 4; i++)
#pragma unroll
                    for (int j = 0; j < 4; j++)
                        sf[i][j] = fmaf(ar[i], br[j], sf[i][j]);
            }

            float mnew[4], alpha[4];
#pragma unroll
            for (int i = 0; i < 4; i++) {
                float pm = -1e30f;
#pragma unroll
                for (int j = 0; j < 4; j++) { sf[i][j] *= 0.125f; pm = fmaxf(pm, sf[i][j]); }
#pragma unroll
                for (int off = 1; off < 16; off <<= 1)
                    pm = fmaxf(pm, __shfl_xor_sync(0xffffffffu, pm, off, 16));
                mnew[i]  = fmaxf(m_run[i], pm);
                alpha[i] = __expf(m_run[i] - mnew[i]);
                m_run[i] = mnew[i];
            }
#pragma unroll
            for (int i = 0; i < 4; i++) {
                float sum = 0.0f;
#pragma unroll
                for (int j = 0; j < 4; j++) {
                    sf[i][j] = __expf(sf[i][j] - mnew[i]);
                    sum += sf[i][j];
                }
#pragma unroll
                for (int off = 1; off < 16; off <<= 1)
                    sum += __shfl_xor_sync(0xffffffffu, sum, off, 16);
#pragma unroll
                for (int j = 0; j < 4; j++) o[i][j] *= alpha[i];
                l_run[i] = l_run[i] * alpha[i] + sum;
            }

            __syncthreads();
#pragma unroll
            for (int i = 0; i < 4; i++) {
                float4 pv = make_float4(sf[i][0], sf[i][1], sf[i][2], sf[i][3]);
                *(float4*)&KtPs[ty * 4 + i][tx * 4] = pv;
            }
            __syncthreads();

#pragma unroll 8
            for (int k = 0; k < 64; k++) {
                float ar[4];
                ar[0] = KtPs[ty * 4 + 0][k];
                ar[1] = KtPs[ty * 4 + 1][k];
                ar[2] = KtPs[ty * 4 + 2][k];
                ar[3] = KtPs[ty * 4 + 3][k];
                float4 b = *(const float4*)&Vs[k][tx * 4];
                float br[4] = {b.x, b.y, b.z, b.w};
#pragma unroll
                for (int i = 0; i < 4; i++)
#pragma unroll
                    for (int j = 0; j < 4; j++)
                        o[i][j] = fmaf(ar[i], br[j], o[i][j]);
            }
        }

        const int b = bh >> 4, h = bh & 15;
#pragma unroll
        for (int i = 0; i < 4; i++) {
            int s = q0 + ty * 4 + i;
            float inv = 1.0f / l_run[i];
            float4 v = make_float4(o[i][0] * inv, o[i][1] * inv, o[i][2] * inv, o[i][3] * inv);
            *(float4*)&g_AO[((size_t)(b * SS + s)) * DM + h * HD + tx * 4] = v;
        }
        __syncthreads();
    }
#endif
}

// ---------------------------------------------------------------------------
extern "C" void kernel_launch(void* const* d_in, const int* in_sizes, int n_in,
                              void* d_out, int out_size)
{
    (void)in_sizes; (void)n_in; (void)out_size;
    const float* x  = (const float*)d_in[0];
    const float* Wq = (const float*)d_in[1];
    const float* bq = (const float*)d_in[2];
    const float* Wk = (const float*)d_in[3];
    const float* bk = (const float*)d_in[4];
    const float* Wv = (const float*)d_in[5];
    const float* bv = (const float*)d_in[6];
    const float* Wo = (const float*)d_in[7];
    const float* bo = (const float*)d_in[8];
    float* out = (float*)d_out;

    cudaFuncSetAttribute(qkv_tc_kernel, cudaFuncAttributeMaxDynamicSharedMemorySize, DYN_SMEM);
    cudaFuncSetAttribute(out_tc_kernel, cudaFuncAttributeMaxDynamicSharedMemorySize, DYN_SMEM);
    cudaFuncSetAttribute(flash_kernel, cudaFuncAttributeMaxDynamicSharedMemorySize, FLASH_SMEM);

    rope_table_kernel<<<(SS * 32) / 256, 256>>>();
    convert_w_kernel<<<dim3(16, 16, 4), 256>>>(Wq, Wk, Wv, Wo);
    convert_x_kernel<<<(MT * DM) / (8 * 256), 256>>>(x);

    dim3 gq(DM / 128, MT / 256, 3);
    qkv_tc_kernel<<<gq, 256, DYN_SMEM>>>(x, Wq, Wk, Wv, bq, bk, bv);

    int rope_total = BB * NH * SS * 32;
    rope_kernel<<<(rope_total + 255) / 256, 256>>>();

    convert_v_kernel<<<dim3(SS / 64, BB * NH), 256>>>();

    dim3 gf(SS / 128, BB * NH);
    flash_kernel<<<gf, 256, FLASH_SMEM>>>();

    dim3 go(DM / 128, MT / 256, 1);
    out_tc_kernel<<<go, 256, DYN_SMEM>>>(Wo, bo, out);
}

// round 17
// speedup vs baseline: 1.0513x; 1.0513x over previous
#include <cuda_runtime.h>
#include <cuda_bf16.h>
#include <cstdint>
#include <math.h>

#define DM 1024
#define NH 16
#define HD 64
#define BB 2
#define SS 2048
#define MT (BB*SS)   // 4096 rows

// tcgen05 is arch-SPECIFIC (sm_103a). The harness also runs a compute_103
// (non-a) pass where ptxas rejects tcgen05 — guard it out there.
#if defined(__CUDA_ARCH__) && defined(__CUDA_ARCH_FEAT_SM103_ALL)
#define HAS_TC 1
#else
#define HAS_TC 0
#endif

// Scratch (device globals: allocation-free rule). Device-code refs only.
__device__ float g_Q[(size_t)BB*NH*SS*HD];
__device__ float g_K[(size_t)BB*NH*SS*HD];
__device__ float g_V[(size_t)BB*NH*SS*HD];
__device__ float g_AO[(size_t)MT*DM];

// RoPE angle tables (unique angles: [s][i], i in 0..31)
__device__ float g_rcos[(size_t)SS*32];
__device__ float g_rsin[(size_t)SS*32];

// Pre-converted split-bf16 operands (hi + lo), filled by converter kernels.
__device__ __nv_bfloat16 g_Xh[(size_t)MT*DM],  g_Xl[(size_t)MT*DM];
__device__ __nv_bfloat16 g_Wth[(size_t)4*DM*DM], g_Wtl[(size_t)4*DM*DM]; // [z][n][k]
__device__ __nv_bfloat16 g_Qsh[(size_t)BB*NH*SS*HD], g_Qsl[(size_t)BB*NH*SS*HD];
__device__ __nv_bfloat16 g_Ksh[(size_t)BB*NH*SS*HD], g_Ksl[(size_t)BB*NH*SS*HD];
__device__ __nv_bfloat16 g_VTh[(size_t)BB*NH*HD*SS], g_VTl[(size_t)BB*NH*HD*SS]; // [bh][d][s]
__device__ __nv_bfloat16 g_AOh[(size_t)MT*DM], g_AOl[(size_t)MT*DM];

// split two fp32 into packed bf16x2 hi word + lo word
__device__ __forceinline__ void split2(float a, float b, uint32_t& h2, uint32_t& l2)
{
    __nv_bfloat16 ha = __float2bfloat16(a), hb = __float2bfloat16(b);
    h2 = ((uint32_t)__bfloat16_as_ushort(hb) << 16) | (uint32_t)__bfloat16_as_ushort(ha);
    __nv_bfloat16 la = __float2bfloat16(a - __bfloat162float(ha));
    __nv_bfloat16 lb = __float2bfloat16(b - __bfloat162float(hb));
    l2 = ((uint32_t)__bfloat16_as_ushort(lb) << 16) | (uint32_t)__bfloat16_as_ushort(la);
}

// fast exp via 2^f polynomial (FMA pipe, not MUFU). Valid |x| < ~80, rel err ~2e-6.
__device__ __forceinline__ float fast_exp(float x)
{
    float y = x * 1.4426950408889634f;
    float r = rintf(y);
    float f = y - r;
    float p = 1.3333558146428443e-3f;
    p = fmaf(p, f, 9.6181291076284772e-3f);
    p = fmaf(p, f, 5.5504108664821580e-2f);
    p = fmaf(p, f, 2.4022650695910072e-1f);
    p = fmaf(p, f, 6.9314718055994531e-1f);
    p = fmaf(p, f, 1.0f);
    return __int_as_float(__float_as_int(p) + (((int)r) << 23));
}

// ============================================================================
// FFMA fallback GEMM core (proven R5) — compiles on every pass.
// ============================================================================
__device__ __forceinline__ void gemm_core(
    const float* __restrict__ A, const float* __restrict__ W,
    float (*As)[132], float (*Bs)[128],
    int bm, int bn, float acc[8][8])
{
    const int tid = threadIdx.x;
    const int tx  = tid & 15;
    const int ty  = tid >> 4;
    const int a_row = tid >> 2;
    const int a_k   = (tid & 3) << 2;
    const int b_k   = tid >> 5;
    const int b_n   = (tid & 31) << 2;

    for (int k0 = 0; k0 < DM; k0 += 16) {
#pragma unroll
        for (int i = 0; i < 2; i++) {
            int r = a_row + i * 64;
            float4 v = *(const float4*)(A + (size_t)(bm + r) * DM + k0 + a_k);
            As[a_k + 0][r] = v.x; As[a_k + 1][r] = v.y;
            As[a_k + 2][r] = v.z; As[a_k + 3][r] = v.w;
        }
#pragma unroll
        for (int i = 0; i < 2; i++) {
            int kk = b_k + i * 8;
            *(float4*)&Bs[kk][b_n] =
                *(const float4*)(W + (size_t)(k0 + kk) * DM + bn + b_n);
        }
        __syncthreads();
#pragma unroll
        for (int k = 0; k < 16; k++) {
            float a_reg[8], b_reg[8];
            *(float4*)&a_reg[0] = *(float4*)&As[k][ty * 4];
            *(float4*)&a_reg[4] = *(float4*)&As[k][ty * 4 + 64];
            *(float4*)&b_reg[0] = *(float4*)&Bs[k][tx * 4];
            *(float4*)&b_reg[4] = *(float4*)&Bs[k][tx * 4 + 64];
#pragma unroll
            for (int i = 0; i < 8; i++)
#pragma unroll
                for (int j = 0; j < 8; j++)
                    acc[i][j] = fmaf(a_reg[i], b_reg[j], acc[i][j]);
        }
        __syncthreads();
    }
}

#if HAS_TC
// ============================================================================
// PTX helpers (sm_103a pass only)
// ============================================================================
__device__ __forceinline__ uint32_t smem_to_u32(const void* p) {
    uint32_t a;
    asm("{ .reg .u64 t; cvta.to.shared.u64 t, %1; cvt.u32.u64 %0, t; }"
        : "=r"(a) : "l"(p));
    return a;
}

#define SMEM_SWIZZLE_128B(off) ((off) ^ (((off) >> 3) & 0x70))

static constexpr uint64_t SMEM_DESC_BASE_SW128 =
    (uint64_t(2)  << 61) | (uint64_t(1) << 46) | (uint64_t(64) << 32) | (uint64_t(1) << 16);
#define MAKE_SMEM_DESC(base_addr) \
    (SMEM_DESC_BASE_SW128 | ((uint64_t)((base_addr) >> 4) & 0x3FFF))

#define TCGEN05_ALLOC(smem_result_addr, nCols) \
    asm volatile("tcgen05.alloc.cta_group::1.sync.aligned.shared::cta.b32 [%0], %1;" \
        :: "r"((uint32_t)(smem_result_addr)), "r"((uint32_t)(nCols)) : "memory")
#define TCGEN05_DEALLOC(tmem_addr, nCols) \
    asm volatile("tcgen05.dealloc.cta_group::1.sync.aligned.b32 %0, %1;" \
        :: "r"(tmem_addr), "r"((uint32_t)(nCols)))
#define TCGEN05_COMMIT(mbar) \
    asm volatile("tcgen05.commit.cta_group::1.mbarrier::arrive::one.shared::cluster.b64 [%0];" \
        :: "r"((uint32_t)(mbar)) : "memory")
#define TCGEN05_WAIT_LD() asm volatile("tcgen05.wait::ld.sync.aligned;" ::: "memory")
#define TCGEN05_WAIT_ST() asm volatile("tcgen05.wait::st.sync.aligned;" ::: "memory")
#define TCGEN05_FENCE_BEFORE() asm volatile("tcgen05.fence::before_thread_sync;" ::: "memory")
#define TCGEN05_FENCE_AFTER() asm volatile("tcgen05.fence::after_thread_sync;" ::: "memory")
#define FENCE_PROXY_ASYNC_SHARED_CTA() \
    asm volatile("fence.proxy.async.shared::cta;" ::: "memory")
#define MBARRIER_INIT(mbar, count) \
    asm volatile("mbarrier.init.shared.b64 [%0], %1;" \
        :: "r"((uint32_t)(mbar)), "r"((uint32_t)(count)) : "memory")

#define MBARRIER_WAIT_PARITY(mbar, parity) do {                                   \
    uint32_t _m = (uint32_t)(mbar); uint32_t _p = (uint32_t)(parity);             \
    uint32_t _done;                                                               \
    asm volatile("{\n\t.reg .pred p;\n\t"                                         \
        "mbarrier.try_wait.parity.acquire.cta.shared::cta.b64 p, [%1], %2;\n\t"   \
        "selp.b32 %0, 1, 0, p;\n\t}"                                              \
        : "=r"(_done) : "r"(_m), "r"(_p) : "memory");                             \
    if (!_done) {                                                                 \
        asm volatile("{\n\t.reg .pred P1;\n\t"                                    \
            "WAIT_LOOP_%=:\n\t"                                                   \
            "mbarrier.try_wait.parity.acquire.cta.shared::cta.b64 P1, [%0], %1, 0x989680;\n\t" \
            "@P1 bra.uni WAIT_DONE_%=;\n\t"                                       \
            "bra.uni WAIT_LOOP_%=;\n\t"                                           \
            "WAIT_DONE_%=:\n\t}"                                                  \
            :: "r"(_m), "r"(_p) : "memory");                                      \
    }                                                                             \
} while (0)

#define TCGEN05_LD_32X32B_X32(r, tmem_addr) \
    asm volatile( \
        "tcgen05.ld.sync.aligned.32x32b.x32.b32 " \
        "{%0, %1, %2, %3, %4, %5, %6, %7, " \
        " %8, %9, %10, %11, %12, %13, %14, %15, " \
        " %16, %17, %18, %19, %20, %21, %22, %23, " \
        " %24, %25, %26, %27, %28, %29, %30, %31}, [%32];" \
        : "=r"((r)[0]),  "=r"((r)[1]),  "=r"((r)[2]),  "=r"((r)[3]), \
          "=r"((r)[4]),  "=r"((r)[5]),  "=r"((r)[6]),  "=r"((r)[7]), \
          "=r"((r)[8]),  "=r"((r)[9]),  "=r"((r)[10]), "=r"((r)[11]), \
          "=r"((r)[12]), "=r"((r)[13]), "=r"((r)[14]), "=r"((r)[15]), \
          "=r"((r)[16]), "=r"((r)[17]), "=r"((r)[18]), "=r"((r)[19]), \
          "=r"((r)[20]), "=r"((r)[21]), "=r"((r)[22]), "=r"((r)[23]), \
          "=r"((r)[24]), "=r"((r)[25]), "=r"((r)[26]), "=r"((r)[27]), \
          "=r"((r)[28]), "=r"((r)[29]), "=r"((r)[30]), "=r"((r)[31]) \
        : "r"(tmem_addr))

#define TCGEN05_ST_32X32B_X32(tmem_addr, r) \
    asm volatile( \
        "tcgen05.st.sync.aligned.32x32b.x32.b32 [%0], " \
        "{%1, %2, %3, %4, %5, %6, %7, %8, " \
        " %9, %10, %11, %12, %13, %14, %15, %16, " \
        " %17, %18, %19, %20, %21, %22, %23, %24, " \
        " %25, %26, %27, %28, %29, %30, %31, %32};" \
        :: "r"(tmem_addr), \
           "r"((r)[0]),  "r"((r)[1]),  "r"((r)[2]),  "r"((r)[3]), \
           "r"((r)[4]),  "r"((r)[5]),  "r"((r)[6]),  "r"((r)[7]), \
           "r"((r)[8]),  "r"((r)[9]),  "r"((r)[10]), "r"((r)[11]), \
           "r"((r)[12]), "r"((r)[13]), "r"((r)[14]), "r"((r)[15]), \
           "r"((r)[16]), "r"((r)[17]), "r"((r)[18]), "r"((r)[19]), \
           "r"((r)[20]), "r"((r)[21]), "r"((r)[22]), "r"((r)[23]), \
           "r"((r)[24]), "r"((r)[25]), "r"((r)[26]), "r"((r)[27]), \
           "r"((r)[28]), "r"((r)[29]), "r"((r)[30]), "r"((r)[31]) \
        : "memory")

// X16 store (pattern mirrored from ptx_helpers TCGEN05_ST_32X32B_X16)
#define TCGEN05_ST_32X32B_X16(tmem_addr, r) \
    asm volatile( \
        "tcgen05.st.sync.aligned.32x32b.x16.b32 [%0], " \
        "{%1, %2, %3, %4, %5, %6, %7, %8, " \
        " %9, %10, %11, %12, %13, %14, %15, %16};" \
        :: "r"(tmem_addr), \
           "r"((r)[0]),  "r"((r)[1]),  "r"((r)[2]),  "r"((r)[3]), \
           "r"((r)[4]),  "r"((r)[5]),  "r"((r)[6]),  "r"((r)[7]), \
           "r"((r)[8]),  "r"((r)[9]),  "r"((r)[10]), "r"((r)[11]), \
           "r"((r)[12]), "r"((r)[13]), "r"((r)[14]), "r"((r)[15]) \
        : "memory")

__device__ __forceinline__ void mma_bf16_ss(
    uint32_t d_tmem, uint64_t a_desc, uint64_t b_desc, uint32_t idesc, uint32_t enable)
{
    asm volatile(
        "{\n\t.reg .pred p;\n\t"
        "setp.ne.u32 p, %5, 0;\n\t"
        "tcgen05.mma.cta_group::1.kind::f16 [%0], %1, %2, %3, {%4, %4, %4, %4}, p;\n\t"
        "}"
        :: "r"(d_tmem), "l"(a_desc), "l"(b_desc), "r"(idesc), "r"(0u), "r"(enable)
        : "memory");
}

__device__ __forceinline__ void mma_bf16_ts(
    uint32_t d_tmem, uint32_t a_tmem, uint64_t b_desc, uint32_t idesc, uint32_t enable)
{
    asm volatile(
        "{\n\t.reg .pred p;\n\t"
        "setp.ne.u32 p, %5, 0;\n\t"
        "tcgen05.mma.cta_group::1.kind::f16 [%0], [%1], %2, %3, {%4, %4, %4, %4}, p;\n\t"
        "}"
        :: "r"(d_tmem), "r"(a_tmem), "l"(b_desc), "r"(idesc), "r"(0u), "r"(enable)
        : "memory");
}

static constexpr uint32_t MMA_IDESC =           // N=128, M=128
    (1u << 4) | (1u << 7) | (1u << 10) | ((128u / 8) << 17) | ((128u / 16) << 24);
static constexpr uint32_t IDESC_PV =            // N=64, M=128
    (1u << 4) | (1u << 7) | (1u << 10) | ((64u / 8) << 17) | ((128u / 16) << 24);
#endif  // HAS_TC

// GEMM stage (M=256 tiles): Ah 32K | Al 32K | Bh 16K | Bl 16K = 96K
#define STAGE_SZ 98304
#define DYN_SMEM (1024 + 2*STAGE_SZ)     // 197632

#if HAS_TC
// ============================================================================
// Tensor-core GEMM tile, M=256 x N=128 (unchanged from passing R15)
// ============================================================================
__device__ void tc_gemm_tile(
    const __nv_bfloat16* __restrict__ Ah, const __nv_bfloat16* __restrict__ Al,
    const __nv_bfloat16* __restrict__ Bh, const __nv_bfloat16* __restrict__ Bl,
    char* sm, uint32_t smb, int bm, int bn, uint32_t tmem)
{
    const int tid = threadIdx.x;
    int phase0 = 0, phase1 = 0;

    for (int c = 0; c < 16; c++) {
        const int stg = c & 1;
        if (c >= 2) {
            if (stg == 0) { MBARRIER_WAIT_PARITY(smb + 16, phase0); phase0 ^= 1; }
            else          { MBARRIER_WAIT_PARITY(smb + 24, phase1); phase1 ^= 1; }
        }
        char* As_h = sm + 1024 + stg * STAGE_SZ;   // 256 rows x 128B
        char* As_l = As_h + 32768;
        char* Bs_h = As_h + 65536;                 // 128 rows x 128B
        char* Bs_l = As_h + 81920;

#pragma unroll
        for (int i = 0; i < 8; i++) {
            int lin = tid + 256 * i;
            int row = lin >> 3, kf = lin & 7;
            uint32_t sw = SMEM_SWIZZLE_128B((uint32_t)(row * 128 + kf * 16));
            size_t ga = (size_t)(bm + row) * DM + c * 64 + kf * 8;
            *(uint4*)(As_h + sw) = *(const uint4*)(Ah + ga);
            *(uint4*)(As_l + sw) = *(const uint4*)(Al + ga);
        }
#pragma unroll
        for (int i = 0; i < 4; i++) {
            int lin = tid + 256 * i;
            int row = lin >> 3, kf = lin & 7;
            uint32_t sw = SMEM_SWIZZLE_128B((uint32_t)(row * 128 + kf * 16));
            size_t gb = (size_t)(bn + row) * DM + c * 64 + kf * 8;
            *(uint4*)(Bs_h + sw) = *(const uint4*)(Bh + gb);
            *(uint4*)(Bs_l + sw) = *(const uint4*)(Bl + gb);
        }
        __syncthreads();

        if (tid == 0) {
            FENCE_PROXY_ASYNC_SHARED_CTA();
            uint64_t dah  = MAKE_SMEM_DESC(smb + 1024 + stg * STAGE_SZ);
            uint64_t dah2 = dah + (16384 >> 4);   // A rows 128-255
            uint64_t dal  = dah + (32768 >> 4);
            uint64_t dal2 = dal + (16384 >> 4);
            uint64_t dbh  = dah + (65536 >> 4);
            uint64_t dbl  = dah + (81920 >> 4);
            uint32_t en = (c != 0);
#pragma unroll
            for (int ks = 0; ks < 4; ks++) {
                uint64_t off = ks * 2;
                uint32_t e = (ks == 0) ? en : 1;
                mma_bf16_ss(tmem,       dah  + off, dbh + off, MMA_IDESC, e);
                mma_bf16_ss(tmem,       dah  + off, dbl + off, MMA_IDESC, 1);
                mma_bf16_ss(tmem,       dal  + off, dbh + off, MMA_IDESC, 1);
                mma_bf16_ss(tmem + 128, dah2 + off, dbh + off, MMA_IDESC, e);
                mma_bf16_ss(tmem + 128, dah2 + off, dbl + off, MMA_IDESC, 1);
                mma_bf16_ss(tmem + 128, dal2 + off, dbh + off, MMA_IDESC, 1);
            }
            TCGEN05_COMMIT(smb + 16 + stg * 8);
        }
    }
    MBARRIER_WAIT_PARITY(smb + 16, phase0);
    MBARRIER_WAIT_PARITY(smb + 24, phase1);
    TCGEN05_FENCE_AFTER();
}
#endif  // HAS_TC

// ============================================================================
// Converter kernels (unchanged)
// ============================================================================

__global__ __launch_bounds__(256) void convert_w_kernel(
    const float* __restrict__ Wq, const float* __restrict__ Wk,
    const float* __restrict__ Wv, const float* __restrict__ Wo)
{
    __shared__ float tile[64 * 65];
    const int z = blockIdx.z;
    const float* W = (z == 0) ? Wq : (z == 1) ? Wk : (z == 2) ? Wv : Wo;
    const int kt = blockIdx.x, nt = blockIdx.y;

#pragma unroll
    for (int i = 0; i < 16; i++) {
        int lin = threadIdx.x + 256 * i;
        int r = lin >> 6, cc = lin & 63;
        tile[r * 65 + cc] = W[(size_t)(kt * 64 + r) * DM + nt * 64 + cc];
    }
    __syncthreads();
#pragma unroll
    for (int i = 0; i < 2; i++) {
        int lin = threadIdx.x + 256 * i;
        int n = lin >> 3, kg = lin & 7;
        float v[8];
#pragma unroll
        for (int j = 0; j < 8; j++) v[j] = tile[(kg * 8 + j) * 65 + n];
        uint4 H, L;
        split2(v[0], v[1], H.x, L.x); split2(v[2], v[3], H.y, L.y);
        split2(v[4], v[5], H.z, L.z); split2(v[6], v[7], H.w, L.w);
        size_t o = ((size_t)z * DM + nt * 64 + n) * DM + kt * 64 + kg * 8;
        *(uint4*)(g_Wth + o) = H;
        *(uint4*)(g_Wtl + o) = L;
    }
}

__global__ __launch_bounds__(256) void convert_x_kernel(const float* __restrict__ x)
{
    size_t g = ((size_t)blockIdx.x * 256 + threadIdx.x) * 8;
    float4 v0 = *(const float4*)(x + g);
    float4 v1 = *(const float4*)(x + g + 4);
    uint4 H, L;
    split2(v0.x, v0.y, H.x, L.x); split2(v0.z, v0.w, H.y, L.y);
    split2(v1.x, v1.y, H.z, L.z); split2(v1.z, v1.w, H.w, L.w);
    *(uint4*)(g_Xh + g) = H;
    *(uint4*)(g_Xl + g) = L;
}

__global__ __launch_bounds__(256) void convert_v_kernel()
{
    __shared__ float tile[64 * 65];
    const int bh = blockIdx.y;
    const int s0 = blockIdx.x * 64;
    const float* V = g_V + (size_t)bh * SS * HD;

#pragma unroll
    for (int i = 0; i < 16; i++) {
        int lin = threadIdx.x + 256 * i;
        int r = lin >> 6, d = lin & 63;
        tile[r * 65 + d] = V[(size_t)(s0 + r) * HD + d];
    }
    __syncthreads();
#pragma unroll
    for (int i = 0; i < 2; i++) {
        int lin = threadIdx.x + 256 * i;
        int d = lin >> 3, sg = lin & 7;
        float v[8];
#pragma unroll
        for (int j = 0; j < 8; j++) v[j] = tile[(sg * 8 + j) * 65 + d];
        uint4 H, L;
        split2(v[0], v[1], H.x, L.x); split2(v[2], v[3], H.y, L.y);
        split2(v[4], v[5], H.z, L.z); split2(v[6], v[7], H.w, L.w);
        size_t o = ((size_t)bh * HD + d) * SS + s0 + sg * 8;
        *(uint4*)(g_VTh + o) = H;
        *(uint4*)(g_VTl + o) = L;
    }
}

// ---------------------------------------------------------------------------
// QKV projection (M=256 tiles, unchanged from passing R15)
// ---------------------------------------------------------------------------
__global__ __launch_bounds__(256, 1) void qkv_tc_kernel(
    const float* __restrict__ X,
    const float* __restrict__ Wq, const float* __restrict__ Wk, const float* __restrict__ Wv,
    const float* __restrict__ bq, const float* __restrict__ bk, const float* __restrict__ bv)
{
    extern __shared__ char sm[];
    const float* Wf; const float* bias; float* outp;
    if (blockIdx.z == 0)      { Wf = Wq; bias = bq; outp = g_Q; }
    else if (blockIdx.z == 1) { Wf = Wk; bias = bk; outp = g_K; }
    else                      { Wf = Wv; bias = bv; outp = g_V; }

    const int bm = blockIdx.y * 256, bn = blockIdx.x * 128;

#if HAS_TC
    (void)X; (void)Wf;
    const uint32_t smb = smem_to_u32(sm);
    const int tid = threadIdx.x, wid = tid >> 5, lane = tid & 31;

    if (wid == 0) TCGEN05_ALLOC(smb + 0, 512);
    if (tid == 0) { MBARRIER_INIT(smb + 16, 1); MBARRIER_INIT(smb + 24, 1); }
    __syncthreads();
    uint32_t tmem;
    asm volatile("ld.shared.b32 %0, [%1];" : "=r"(tmem) : "r"(smb + 0));

    const __nv_bfloat16* Bh = g_Wth + (size_t)blockIdx.z * DM * DM;
    const __nv_bfloat16* Bl = g_Wtl + (size_t)blockIdx.z * DM * DM;
    tc_gemm_tile(g_Xh, g_Xl, Bh, Bl, sm, smb, bm, bn, tmem);

    {
        const int mh = wid >> 2, sp = wid & 3;
        float* ep = (float*)(sm + 1024 + wid * 4352);
#pragma unroll
        for (int nc = 0; nc < 4; nc++) {
            uint32_t r[32];
            TCGEN05_LD_32X32B_X32(r, tmem + mh * 128 + nc * 32);
            TCGEN05_WAIT_LD();
#pragma unroll
            for (int cc = 0; cc < 32; cc++) ep[lane * 33 + cc] = __uint_as_float(r[cc]);
            __syncwarp();
            int n = bn + nc * 32 + lane;
            float bval = bias[n];
            int h = n >> 6, dh = n & 63;
#pragma unroll
            for (int rr = 0; rr < 32; rr++) {
                int m = bm + mh * 128 + sp * 32 + rr;
                int b = m >> 11, s = m & (SS - 1);
                outp[(((size_t)(b * NH + h)) * SS + s) * HD + dh] = ep[rr * 33 + lane] + bval;
            }
            __syncwarp();
        }
    }
    __syncthreads();
    if (wid == 0) TCGEN05_DEALLOC(tmem, 512);
#else
    float (*As)[132] = (float(*)[132])sm;
    float (*Bs)[128] = (float(*)[128])(sm + 16 * 132 * 4);
    const int tx = threadIdx.x & 15, ty = threadIdx.x >> 4;
    for (int h2 = 0; h2 < 2; h2++) {
        float acc[8][8] = {};
        gemm_core(X, Wf, As, Bs, bm + h2 * 128, bn, acc);
#pragma unroll
        for (int i = 0; i < 8; i++) {
            int m = bm + h2 * 128 + ty * 4 + (i & 3) + (i >> 2) * 64;
            int b = m >> 11, s = m & (SS - 1);
#pragma unroll
            for (int j = 0; j < 8; j++) {
                int n  = bn + tx * 4 + (j & 3) + (j >> 2) * 64;
                int h  = n >> 6, dh = n & 63;
                outp[(((size_t)(b * NH + h)) * SS + s) * HD + dh] = acc[i][j] + bias[n];
            }
        }
        __syncthreads();
    }
#endif
}

// ---------------------------------------------------------------------------
// Output projection (M=256 tiles, unchanged from passing R15)
// ---------------------------------------------------------------------------
__global__ __launch_bounds__(256, 1) void out_tc_kernel(
    const float* __restrict__ W, const float* __restrict__ bias, float* __restrict__ outp)
{
    extern __shared__ char sm[];
    const int bm = blockIdx.y * 256, bn = blockIdx.x * 128;

#if HAS_TC
    (void)W;
    const uint32_t smb = smem_to_u32(sm);
    const int tid = threadIdx.x, wid = tid >> 5, lane = tid & 31;

    if (wid == 0) TCGEN05_ALLOC(smb + 0, 512);
    if (tid == 0) { MBARRIER_INIT(smb + 16, 1); MBARRIER_INIT(smb + 24, 1); }
    __syncthreads();
    uint32_t tmem;
    asm volatile("ld.shared.b32 %0, [%1];" : "=r"(tmem) : "r"(smb + 0));

    tc_gemm_tile(g_AOh, g_AOl, g_Wth + (size_t)3 * DM * DM, g_Wtl + (size_t)3 * DM * DM,
                 sm, smb, bm, bn, tmem);

    {
        const int mh = wid >> 2, sp = wid & 3;
        float* ep = (float*)(sm + 1024 + wid * 4352);
#pragma unroll
        for (int nc = 0; nc < 4; nc++) {
            uint32_t r[32];
            TCGEN05_LD_32X32B_X32(r, tmem + mh * 128 + nc * 32);
            TCGEN05_WAIT_LD();
#pragma unroll
            for (int cc = 0; cc < 32; cc++) ep[lane * 33 + cc] = __uint_as_float(r[cc]);
            __syncwarp();
            int n = bn + nc * 32 + lane;
            float bval = bias[n];
#pragma unroll
            for (int rr = 0; rr < 32; rr++) {
                int m = bm + mh * 128 + sp * 32 + rr;
                outp[(size_t)m * DM + n] = ep[rr * 33 + lane] + bval;
            }
            __syncwarp();
        }
    }
    __syncthreads();
    if (wid == 0) TCGEN05_DEALLOC(tmem, 512);
#else
    float (*As)[132] = (float(*)[132])sm;
    float (*Bs)[128] = (float(*)[128])(sm + 16 * 132 * 4);
    const int tx = threadIdx.x & 15, ty = threadIdx.x >> 4;
    for (int h2 = 0; h2 < 2; h2++) {
        float acc[8][8] = {};
        gemm_core(g_AO, W, As, Bs, bm + h2 * 128, bn, acc);
#pragma unroll
        for (int i = 0; i < 8; i++) {
            int m = bm + h2 * 128 + ty * 4 + (i & 3) + (i >> 2) * 64;
#pragma unroll
            for (int j = 0; j < 8; j++) {
                int n = bn + tx * 4 + (j & 3) + (j >> 2) * 64;
                outp[(size_t)m * DM + n] = acc[i][j] + bias[n];
            }
        }
        __syncthreads();
    }
#endif
}

// ---------------------------------------------------------------------------
// RoPE: angle table + memory-bound apply (unchanged)
// ---------------------------------------------------------------------------
__global__ __launch_bounds__(256) void rope_table_kernel()
{
    int idx = blockIdx.x * blockDim.x + threadIdx.x;
    int i = idx & 31;
    int s = idx >> 5;
    float invf = powf(10000.0f, -((float)(2 * i)) / (float)HD);
    float th   = (float)s * invf;
    g_rcos[idx] = (float)cos((double)th);
    g_rsin[idx] = (float)sin((double)th);
}

__global__ __launch_bounds__(256) void rope_kernel()
{
    int idx = blockIdx.x * blockDim.x + threadIdx.x;
    const int total = BB * NH * SS * 32;
    if (idx >= total) return;
    int i   = idx & 31;
    int bhs = idx >> 5;
    int s   = bhs & (SS - 1);

    float c  = g_rcos[s * 32 + i];
    float sn = g_rsin[s * 32 + i];

    size_t base = (size_t)bhs * HD;
    float q0 = g_Q[base + i], q1 = g_Q[base + i + 32];
    float k0 = g_K[base + i], k1 = g_K[base + i + 32];
    float qa = q0 * c - q1 * sn, qb = q1 * c + q0 * sn;
    float ka = k0 * c - k1 * sn, kb = k1 * c + k0 * sn;
#if HAS_TC
    qa *= 0.125f; qb *= 0.125f;
    __nv_bfloat16 h;
    h = __float2bfloat16(qa); g_Qsh[base + i]      = h; g_Qsl[base + i]      = __float2bfloat16(qa - __bfloat162float(h));
    h = __float2bfloat16(qb); g_Qsh[base + i + 32] = h; g_Qsl[base + i + 32] = __float2bfloat16(qb - __bfloat162float(h));
    h = __float2bfloat16(ka); g_Ksh[base + i]      = h; g_Ksl[base + i]      = __float2bfloat16(ka - __bfloat162float(h));
    h = __float2bfloat16(kb); g_Ksh[base + i + 32] = h; g_Ksl[base + i + 32] = __float2bfloat16(kb - __bfloat162float(h));
#else
    g_Q[base + i] = qa; g_Q[base + i + 32] = qb;
    g_K[base + i] = ka; g_K[base + i + 32] = kb;
#endif
}

// ---------------------------------------------------------------------------
// Flash attention. TC path: R13/R15 pipelined schedule (single S buffer),
// now with 512 THREADS (16 warps) — softmax split into 32-column chunks:
// warp w handles subpartition w&3, column chunk w>>2. Halves per-warp
// softmax latency exposure and doubles loader parallelism.
// ---------------------------------------------------------------------------
#define OFF_QH 1024
#define OFF_QL (OFF_QH + 16384)
#define OFF_S0 (OFF_QL + 16384)          // stage base: 33792
#define FSTG 65536
#define FLASH_SMEM (OFF_S0 + 2*FSTG)     // 164864
#define TM_S 0
#define TM_O 128
#define TM_PH 192
#define TM_PL 256

__global__ __launch_bounds__(512, 1) void flash_kernel()
{
#if HAS_TC
    extern __shared__ char sm[];
    const uint32_t smb = smem_to_u32(sm);
    const int tid = threadIdx.x, wid = tid >> 5, lane = tid & 31;
    const int bh = blockIdx.y;
    const int q0 = blockIdx.x * 128;

    if (wid == 0) TCGEN05_ALLOC(smb + 0, 512);
    if (tid == 0) { MBARRIER_INIT(smb + 8, 1); MBARRIER_INIT(smb + 16, 1); }
    __syncthreads();
    uint32_t tmem;
    asm volatile("ld.shared.b32 %0, [%1];" : "=r"(tmem) : "r"(smb + 0));

    // Q tile copy (pre-scaled, pre-split): 1024 uint4 per tensor, 512 threads
#pragma unroll
    for (int i = 0; i < 2; i++) {
        int lin = tid + 512 * i;
        int row = lin >> 3, kf = lin & 7;
        uint32_t sw = SMEM_SWIZZLE_128B((uint32_t)(row * 128 + kf * 16));
        size_t ga = ((size_t)bh * SS + q0 + row) * HD + kf * 8;
        *(uint4*)(sm + OFF_QH + sw) = *(const uint4*)(g_Qsh + ga);
        *(uint4*)(sm + OFF_QL + sw) = *(const uint4*)(g_Qsl + ga);
    }

    // stage loader: K split + V (pre-transposed [d][s]) split into stage st
    auto load_stage = [&](int kt, int st) {
        char* base = sm + OFF_S0 + st * FSTG;
#pragma unroll
        for (int i = 0; i < 2; i++) {
            int lin = tid + 512 * i;
            int row = lin >> 3, kf = lin & 7;
            uint32_t sw = SMEM_SWIZZLE_128B((uint32_t)(row * 128 + kf * 16));
            size_t ga = ((size_t)bh * SS + kt * 128 + row) * HD + kf * 8;
            *(uint4*)(base + sw)         = *(const uint4*)(g_Ksh + ga);
            *(uint4*)(base + 16384 + sw) = *(const uint4*)(g_Ksl + ga);
        }
#pragma unroll
        for (int i = 0; i < 2; i++) {
            int lin = tid + 512 * i;
            int d = lin >> 4, kg = lin & 15;
            int sub = kg >> 3;
            uint32_t sw = SMEM_SWIZZLE_128B((uint32_t)(d * 128 + (kg & 7) * 16));
            size_t ga = ((size_t)bh * HD + d) * SS + kt * 128 + kg * 8;
            *(uint4*)(base + 32768 + sub * 8192 + sw) = *(const uint4*)(g_VTh + ga);
            *(uint4*)(base + 49152 + sub * 8192 + sw) = *(const uint4*)(g_VTl + ga);
        }
    };

    const uint64_t qh_d = MAKE_SMEM_DESC(smb + OFF_QH);
    const uint64_t ql_d = MAKE_SMEM_DESC(smb + OFF_QL);

    // prologue: stage 0 holds kt=0
    load_stage(0, 0);
    __syncthreads();

    float lrow = 0.0f;
    int ph_s = 0, ph_o = 0;

    for (int kt = 0; kt < SS / 128; kt++) {
        const int st = kt & 1;
        const uint32_t stb = smb + OFF_S0 + st * FSTG;

        // issue S(kt) — operands in stage st were synced last iteration
        if (tid == 0) {
            FENCE_PROXY_ASYNC_SHARED_CTA();
            uint64_t kh_d = MAKE_SMEM_DESC(stb);
            uint64_t kl_d = MAKE_SMEM_DESC(stb + 16384);
            uint32_t en = 0;
#pragma unroll
            for (int ks = 0; ks < 4; ks++) {
                uint64_t off = ks * 2;
                mma_bf16_ss(tmem + TM_S, qh_d + off, kh_d + off, MMA_IDESC, en); en = 1;
                mma_bf16_ss(tmem + TM_S, qh_d + off, kl_d + off, MMA_IDESC, 1);
                mma_bf16_ss(tmem + TM_S, ql_d + off, kh_d + off, MMA_IDESC, 1);
            }
            TCGEN05_COMMIT(smb + 8);
        }

        // wait PV(kt-1) before overwriting stage 1-st's V, then prefetch kt+1
        if (kt > 0) { MBARRIER_WAIT_PARITY(smb + 16, ph_o); ph_o ^= 1; }
        if (kt + 1 < SS / 128) load_stage(kt + 1, 1 - st);

        // wait S(kt)
        MBARRIER_WAIT_PARITY(smb + 8, ph_s); ph_s ^= 1;
        TCGEN05_FENCE_AFTER();

        // softmax: 16 warps; warp w = subpartition w&3, column chunk w>>2 (32 cols)
        {
            const uint32_t woff = (uint32_t)(wid & 3) << 21;
            const int ck = wid >> 2;                     // 0..3
            uint32_t s0[32];
            TCGEN05_LD_32X32B_X32(s0, tmem + TM_S + ck * 32);
            TCGEN05_WAIT_LD();
            uint32_t phw[16], plw[16];
#pragma unroll
            for (int w = 0; w < 16; w++) {
                float pe = fast_exp(__uint_as_float(s0[2 * w]));
                float pd = fast_exp(__uint_as_float(s0[2 * w + 1]));
                lrow += pe + pd;
                split2(pe, pd, phw[w], plw[w]);
            }
            TCGEN05_ST_32X32B_X16(tmem + TM_PH + ck * 16 + woff, phw);
            TCGEN05_ST_32X32B_X16(tmem + TM_PL + ck * 16 + woff, plw);
            TCGEN05_WAIT_ST();
            TCGEN05_FENCE_BEFORE();
        }
        __syncthreads();   // all STTM done; also drains this iter's stage loads

        // issue PV(kt) from stage st's V
        if (tid == 0) {
            TCGEN05_FENCE_AFTER();
            uint64_t vth_d0 = MAKE_SMEM_DESC(stb + 32768);
            uint64_t vth_d1 = MAKE_SMEM_DESC(stb + 32768 + 8192);
            uint64_t vtl_d0 = MAKE_SMEM_DESC(stb + 49152);
            uint64_t vtl_d1 = MAKE_SMEM_DESC(stb + 49152 + 8192);
            uint32_t en = (kt != 0);
#pragma unroll
            for (int ks = 0; ks < 8; ks++) {
                uint32_t a_off = ks * 8;
                uint64_t b_off = (uint64_t)(ks & 3) * 2;
                uint64_t bh_dsc = (ks < 4 ? vth_d0 : vth_d1) + b_off;
                uint64_t bl_dsc = (ks < 4 ? vtl_d0 : vtl_d1) + b_off;
                mma_bf16_ts(tmem + TM_O, tmem + TM_PH + a_off, bh_dsc, IDESC_PV, en); en = 1;
                mma_bf16_ts(tmem + TM_O, tmem + TM_PH + a_off, bl_dsc, IDESC_PV, 1);
                mma_bf16_ts(tmem + TM_O, tmem + TM_PL + a_off, bh_dsc, IDESC_PV, 1);
            }
            TCGEN05_COMMIT(smb + 16);
        }
    }

    MBARRIER_WAIT_PARITY(smb + 16, ph_o);
    TCGEN05_FENCE_AFTER();

    // combine chunk-sums, normalize, write split-bf16 AO
    __syncthreads();
    float* slr = (float*)(sm + OFF_QH);     // 512 floats
    slr[tid] = lrow;
    __syncthreads();
    if (wid < 4) {
        // row (wid*32 + lane): partials at slr[ck*128 + wid*32 + lane], ck=0..3
        float ltot = slr[tid] + slr[tid + 128] + slr[tid + 256] + slr[tid + 384];
        uint32_t o0[32], o1[32];
        TCGEN05_LD_32X32B_X32(o0, tmem + TM_O);
        TCGEN05_LD_32X32B_X32(o1, tmem + TM_O + 32);
        TCGEN05_WAIT_LD();
        float inv = 1.0f / ltot;
        int b = bh >> 4, h = bh & 15;
        int s = q0 + wid * 32 + lane;
        size_t off = ((size_t)(b * SS + s)) * DM + h * HD;
#pragma unroll
        for (int g = 0; g < 8; g++) {
            float v[8];
#pragma unroll
            for (int j = 0; j < 8; j++) {
                int c = g * 8 + j;
                v[j] = (c < 32 ? __uint_as_float(o0[c]) : __uint_as_float(o1[c - 32])) * inv;
            }
            uint4 H, L;
            split2(v[0], v[1], H.x, L.x); split2(v[2], v[3], H.y, L.y);
            split2(v[4], v[5], H.z, L.z); split2(v[6], v[7], H.w, L.w);
            *(uint4*)(g_AOh + off + g * 8) = H;
            *(uint4*)(g_AOl + off + g * 8) = L;
        }
    }
    __syncthreads();
    if (wid == 0) TCGEN05_DEALLOC(tmem, 512);

#else  // ------- FFMA fallback: R5 flash, 256 working threads -------
    if (threadIdx.x >= 256) return;   // exited threads don't join barriers

    __shared__ float Qt[64][64];
    __shared__ float KtPs[64][64];
    __shared__ float Vs[64][64];

    const int bh = blockIdx.y;
    const float* Qg = g_Q + (size_t)bh * SS * HD;
    const float* Kg = g_K + (size_t)bh * SS * HD;
    const float* Vg = g_V + (size_t)bh * SS * HD;

    const int tid = threadIdx.x;
    const int tx = tid & 15, ty = tid >> 4;
    const int lr = tid >> 2;
    const int lk = (tid & 3) << 2;

    for (int half = 0; half < 2; half++) {
        const int q0 = blockIdx.x * 128 + half * 64;
        __syncthreads();
#pragma unroll
        for (int u = 0; u < 4; u++) {
            int kk = lk + u * 16;
            float4 v = *(const float4*)(Qg + (size_t)(q0 + lr) * HD + kk);
            Qt[kk + 0][lr] = v.x; Qt[kk + 1][lr] = v.y;
            Qt[kk + 2][lr] = v.z; Qt[kk + 3][lr] = v.w;
        }

        float o[4][4] = {};
        float m_run[4], l_run[4];
#pragma unroll
        for (int i = 0; i < 4; i++) { m_run[i] = -1e30f; l_run[i] = 0.0f; }

        for (int kt = 0; kt < SS / 64; kt++) {
            const int kv0 = kt * 64;
            __syncthreads();
#pragma unroll
            for (int u = 0; u < 4; u++) {
                int kk = lk + u * 16;
                float4 v = *(const float4*)(Kg + (size_t)(kv0 + lr) * HD + kk);
                KtPs[kk + 0][lr] = v.x;
                KtPs[kk + 1][lr] = v.y;
                KtPs[kk + 2][lr] = v.z;
                KtPs[kk + 3][lr] = v.w;
                float4 w = *(const float4*)(Vg + (size_t)(kv0 + lr) * HD + kk);
                *(float4*)&Vs[lr][kk] = w;
            }
            __syncthreads();

            float sf[4][4] = {};
#pragma unroll 8
            for (int k = 0; k < 64; k++) {
                float4 a = *(const float4*)&Qt[k][ty * 4];
                float4 b = *(const float4*)&KtPs[k][tx * 4];
                float ar[4] = {a.x, a.y, a.z, a.w};
                float br[4] = {b.x, b.y, b.z, b.w};
#pragma unroll
                for (int i = 0; i < 4; i++)
#pragma unroll
                    for (int j = 0; j < 4; j++)
                        sf[i][j] = fmaf(ar[i], br[j], sf[i][j]);
            }

            float mnew[4], alpha[4];
#pragma unroll
            for (int i = 0; i < 4; i++) {
                float pm = -1e30f;
#pragma unroll
                for (int j = 0; j < 4; j++) { sf[i][j] *= 0.125f; pm = fmaxf(pm, sf[i][j]); }
#pragma unroll
                for (int off = 1; off < 16; off <<= 1)
                    pm = fmaxf(pm, __shfl_xor_sync(0xffffffffu, pm, off, 16));
                mnew[i]  = fmaxf(m_run[i], pm);
                alpha[i] = __expf(m_run[i] - mnew[i]);
                m_run[i] = mnew[i];
            }
#pragma unroll
            for (int i = 0; i < 4; i++) {
                float sum = 0.0f;
#pragma unroll
                for (int j = 0; j < 4; j++) {
                    sf[i][j] = __expf(sf[i][j] - mnew[i]);
                    sum += sf[i][j];
                }
#pragma unroll
                for (int off = 1; off < 16; off <<= 1)
                    sum += __shfl_xor_sync(0xffffffffu, sum, off, 16);
#pragma unroll
                for (int j = 0; j < 4; j++) o[i][j] *= alpha[i];
                l_run[i] = l_run[i] * alpha[i] + sum;
            }

            __syncthreads();
#pragma unroll
            for (int i = 0; i < 4; i++) {
                float4 pv = make_float4(sf[i][0], sf[i][1], sf[i][2], sf[i][3]);
                *(float4*)&KtPs[ty * 4 + i][tx * 4] = pv;
            }
            __syncthreads();

#pragma unroll 8
            for (int k = 0; k < 64; k++) {
                float ar[4];
                ar[0] = KtPs[ty * 4 + 0][k];
                ar[1] = KtPs[ty * 4 + 1][k];
                ar[2] = KtPs[ty * 4 + 2][k];
                ar[3] = KtPs[ty * 4 + 3][k];
                float4 b = *(const float4*)&Vs[k][tx * 4];
                float br[4] = {b.x, b.y, b.z, b.w};
#pragma unroll
                for (int i = 0; i < 4; i++)
#pragma unroll
                    for (int j = 0; j < 4; j++)
                        o[i][j] = fmaf(ar[i], br[j], o[i][j]);
            }
        }

        const int b = bh >> 4, h = bh & 15;
#pragma unroll
        for (int i = 0; i < 4; i++) {
            int s = q0 + ty * 4 + i;
            float inv = 1.0f / l_run[i];
            float4 v = make_float4(o[i][0] * inv, o[i][1] * inv, o[i][2] * inv, o[i][3] * inv);
            *(float4*)&g_AO[((size_t)(b * SS + s)) * DM + h * HD + tx * 4] = v;
        }
        __syncthreads();
    }
#endif
}

// ---------------------------------------------------------------------------
extern "C" void kernel_launch(void* const* d_in, const int* in_sizes, int n_in,
                              void* d_out, int out_size)
{
    (void)in_sizes; (void)n_in; (void)out_size;
    const float* x  = (const float*)d_in[0];
    const float* Wq = (const float*)d_in[1];
    const float* bq = (const float*)d_in[2];
    const float* Wk = (const float*)d_in[3];
    const float* bk = (const float*)d_in[4];
    const float* Wv = (const float*)d_in[5];
    const float* bv = (const float*)d_in[6];
    const float* Wo = (const float*)d_in[7];
    const float* bo = (const float*)d_in[8];
    float* out = (float*)d_out;

    cudaFuncSetAttribute(qkv_tc_kernel, cudaFuncAttributeMaxDynamicSharedMemorySize, DYN_SMEM);
    cudaFuncSetAttribute(out_tc_kernel, cudaFuncAttributeMaxDynamicSharedMemorySize, DYN_SMEM);
    cudaFuncSetAttribute(flash_kernel, cudaFuncAttributeMaxDynamicSharedMemorySize, FLASH_SMEM);

    rope_table_kernel<<<(SS * 32) / 256, 256>>>();
    convert_w_kernel<<<dim3(16, 16, 4), 256>>>(Wq, Wk, Wv, Wo);
    convert_x_kernel<<<(MT * DM) / (8 * 256), 256>>>(x);

    dim3 gq(DM / 128, MT / 256, 3);
    qkv_tc_kernel<<<gq, 256, DYN_SMEM>>>(x, Wq, Wk, Wv, bq, bk, bv);

    int rope_total = BB * NH * SS * 32;
    rope_kernel<<<(rope_total + 255) / 256, 256>>>();

    convert_v_kernel<<<dim3(SS / 64, BB * NH), 256>>>();

    dim3 gf(SS / 128, BB * NH);
    flash_kernel<<<gf, 512, FLASH_SMEM>>>();

    dim3 go(DM / 128, MT / 256, 1);
    out_tc_kernel<<<go, 256, DYN_SMEM>>>(Wo, bo, out);
}